// round 1
// baseline (speedup 1.0000x reference)
#include <cuda_runtime.h>
#include <cuda_bf16.h>
#include <math.h>

// Problem constants (from reference)
#define N_ROWS     8192
#define DIM        256
#define NUM_PIDS   5532
#define NUM_CQ     5000
#define L_TOT      (NUM_PIDS + NUM_CQ)   // 10532
#define IGNORE_IDX 5554
#define OIM_SCALAR 30.0f

// GEMM tiling
#define BM 128
#define BN 128
#define BK 16
#define TM 8
#define TN 8
#define NTHREADS 256               // (BM/TM)*(BN/TN) = 16*16

#define NCB ((L_TOT + BN - 1) / BN)   // 83 column blocks

// Scratch (device globals; no allocation allowed).
// Every slot is fully overwritten each launch -> deterministic, no init needed.
__device__ float g_partial[NCB][N_ROWS];   // per-(colblock,row) sum of exp
__device__ float g_labellogit[N_ROWS];     // logit at label column (unique writer)
__device__ float g_rowloss[N_ROWS];
__device__ float g_rowvalid[N_ROWS];

// ---------------------------------------------------------------------------
// Fused GEMM + exp-rowsum + label-logit capture.
// Block (bn, bm) computes logits for rows [bm*128, ...) x cols [bn*128, ...)
// and reduces exp(logit) over its 128 columns into g_partial[bn][row].
// ---------------------------------------------------------------------------
__global__ __launch_bounds__(NTHREADS)
void oim_gemm_kernel(const float* __restrict__ A,     // inputs [N_ROWS, DIM]
                     const float* __restrict__ lut,   // [NUM_PIDS, DIM]
                     const float* __restrict__ cq,    // [NUM_CQ, DIM]
                     const float* __restrict__ rel,   // [L_TOT]
                     const int*   __restrict__ label) // [N_ROWS]
{
    const int bn = blockIdx.x;            // 0..NCB-1
    const int bm = blockIdx.y;            // 0..63
    const int row0 = bm * BM;
    const int col0 = bn * BN;

    __shared__ float As[BK][BM];
    __shared__ float Bs[BK][BN];
    __shared__ float relS[BN];
    __shared__ int   lblS[BM];

    const int tid = threadIdx.x;
    const int tx = tid & 15;              // column group
    const int ty = tid >> 4;              // row group

    if (tid < BN) {
        int c = col0 + tid;
        relS[tid] = (c < L_TOT) ? rel[c] * OIM_SCALAR : 0.0f;
    }
    if (tid < BM) {
        lblS[tid] = label[row0 + tid];
    }

    float acc[TM][TN];
#pragma unroll
    for (int i = 0; i < TM; i++)
#pragma unroll
        for (int j = 0; j < TN; j++)
            acc[i][j] = 0.0f;

    for (int k0 = 0; k0 < DIM; k0 += BK) {
        // Load A tile: 128 rows x 16 k. 512 float4s, 2 per thread.
#pragma unroll
        for (int i = 0; i < 2; i++) {
            int q = tid + i * NTHREADS;           // 0..511
            int m = q >> 2;
            int kk = (q & 3) * 4;
            float4 v = *reinterpret_cast<const float4*>(
                &A[(size_t)(row0 + m) * DIM + k0 + kk]);
            As[kk + 0][m] = v.x;
            As[kk + 1][m] = v.y;
            As[kk + 2][m] = v.z;
            As[kk + 3][m] = v.w;
        }
        // Load B tile: 128 bank rows (cols of logits) x 16 k.
#pragma unroll
        for (int i = 0; i < 2; i++) {
            int q = tid + i * NTHREADS;
            int n = q >> 2;
            int kk = (q & 3) * 4;
            int c = col0 + n;
            float4 v;
            if (c < NUM_PIDS) {
                v = *reinterpret_cast<const float4*>(
                    &lut[(size_t)c * DIM + k0 + kk]);
            } else if (c < L_TOT) {
                v = *reinterpret_cast<const float4*>(
                    &cq[(size_t)(c - NUM_PIDS) * DIM + k0 + kk]);
            } else {
                v = make_float4(0.f, 0.f, 0.f, 0.f);
            }
            Bs[kk + 0][n] = v.x;
            Bs[kk + 1][n] = v.y;
            Bs[kk + 2][n] = v.z;
            Bs[kk + 3][n] = v.w;
        }
        __syncthreads();

#pragma unroll
        for (int k = 0; k < BK; k++) {
            float a[TM], b[TN];
            float4 a0 = *reinterpret_cast<const float4*>(&As[k][ty * TM]);
            float4 a1 = *reinterpret_cast<const float4*>(&As[k][ty * TM + 4]);
            a[0] = a0.x; a[1] = a0.y; a[2] = a0.z; a[3] = a0.w;
            a[4] = a1.x; a[5] = a1.y; a[6] = a1.z; a[7] = a1.w;
            float4 b0 = *reinterpret_cast<const float4*>(&Bs[k][tx * TN]);
            float4 b1 = *reinterpret_cast<const float4*>(&Bs[k][tx * TN + 4]);
            b[0] = b0.x; b[1] = b0.y; b[2] = b0.z; b[3] = b0.w;
            b[4] = b1.x; b[5] = b1.y; b[6] = b1.z; b[7] = b1.w;
#pragma unroll
            for (int i = 0; i < TM; i++)
#pragma unroll
                for (int j = 0; j < TN; j++)
                    acc[i][j] = fmaf(a[i], b[j], acc[i][j]);
        }
        __syncthreads();
    }

    // Epilogue: logit = acc * rel * 30 ; sum exp over this block's columns,
    // capture label logit.
#pragma unroll
    for (int i = 0; i < TM; i++) {
        int lrow = ty * TM + i;
        int row = row0 + lrow;
        int lbl = lblS[lrow];
        float s = 0.0f;
#pragma unroll
        for (int j = 0; j < TN; j++) {
            int lcol = tx * TN + j;
            int c = col0 + lcol;
            float logit = acc[i][j] * relS[lcol];
            if (c < L_TOT) s += __expf(logit);
            if (c == lbl) g_labellogit[row] = logit;   // unique writer
        }
        // Reduce across the 16 threads (tx) holding this row.
#pragma unroll
        for (int off = 8; off > 0; off >>= 1)
            s += __shfl_down_sync(0xFFFFFFFFu, s, off, 16);
        if (tx == 0)
            g_partial[bn][row] = s;
    }
}

// ---------------------------------------------------------------------------
// Per-row loss: deterministic fixed-order sum over column blocks.
// ---------------------------------------------------------------------------
__global__ void oim_rowloss_kernel(const int* __restrict__ label)
{
    int i = blockIdx.x * blockDim.x + threadIdx.x;
    if (i >= N_ROWS) return;
    float s = 0.0f;
#pragma unroll 4
    for (int b = 0; b < NCB; b++)
        s += g_partial[b][i];
    int lbl = label[i];
    bool valid = (lbl != IGNORE_IDX);
    g_rowloss[i]  = valid ? (logf(s) - g_labellogit[i]) : 0.0f;
    g_rowvalid[i] = valid ? 1.0f : 0.0f;
}

// ---------------------------------------------------------------------------
// Final deterministic reduction (single block, fixed tree).
// ---------------------------------------------------------------------------
__global__ void oim_final_kernel(float* __restrict__ out)
{
    __shared__ float ssum[1024];
    __shared__ float scnt[1024];
    int t = threadIdx.x;
    float s = 0.0f, c = 0.0f;
    for (int i = t; i < N_ROWS; i += 1024) {
        s += g_rowloss[i];
        c += g_rowvalid[i];
    }
    ssum[t] = s;
    scnt[t] = c;
    __syncthreads();
    for (int off = 512; off > 0; off >>= 1) {
        if (t < off) {
            ssum[t] += ssum[t + off];
            scnt[t] += scnt[t + off];
        }
        __syncthreads();
    }
    if (t == 0)
        out[0] = ssum[0] / fmaxf(scnt[0], 1.0f);
}

// ---------------------------------------------------------------------------
extern "C" void kernel_launch(void* const* d_in, const int* in_sizes, int n_in,
                              void* d_out, int out_size)
{
    const float* inputs = (const float*)d_in[0];   // [8192, 256]
    const int*   label  = (const int*)  d_in[1];   // [8192]
    // d_in[2] = ious (unused by reference)
    const float* lut    = (const float*)d_in[3];   // [5532, 256]
    const float* cq     = (const float*)d_in[4];   // [5000, 256]
    const float* rel    = (const float*)d_in[5];   // [10532]
    float* out = (float*)d_out;

    dim3 grid(NCB, N_ROWS / BM);                   // 83 x 64
    oim_gemm_kernel<<<grid, NTHREADS>>>(inputs, lut, cq, rel, label);

    oim_rowloss_kernel<<<(N_ROWS + 255) / 256, 256>>>(label);

    oim_final_kernel<<<1, 1024>>>(out);
}

// round 3
// speedup vs baseline: 5.8913x; 5.8913x over previous
#include <cuda_runtime.h>
#include <cuda_bf16.h>
#include <math.h>
#include <stdint.h>

// ---------------- problem constants ----------------
#define N_ROWS     8192
#define DIM        256
#define NUM_PIDS   5532
#define NUM_CQ     5000
#define L_TOT      (NUM_PIDS + NUM_CQ)   // 10532
#define IGNORE_IDX 5554
#define OIM_SCALAR 30.0f

// ---------------- tiling ----------------
#define BM 128
#define BN 128
#define BK 32
#define NCB ((L_TOT + BN - 1) / BN)      // 83 column blocks
#define B_PAD (NCB * BN)                 // 10624 padded bank rows
#define ASTRIDE 40                       // bf16 elems per smem row (32 + 8 pad)

// ---------------- device scratch (zero-initialized globals) ----------------
__device__ __nv_bfloat16 g_Abf[N_ROWS * DIM];
__device__ __nv_bfloat16 g_Bbf[B_PAD * DIM];   // rows >= L_TOT stay 0 forever
__device__ float g_partial[NCB][N_ROWS];
__device__ float g_labellogit[N_ROWS];
__device__ float g_rowloss[N_ROWS];
__device__ float g_rowvalid[N_ROWS];

// ---------------- PTX helpers (all sm_80+, valid under compute_100) ----------
__device__ __forceinline__ uint32_t smem_u32(const void* p) {
    uint32_t a;
    asm("{ .reg .u64 t; cvta.to.shared.u64 t, %1; cvt.u32.u64 %0, t; }"
        : "=r"(a) : "l"(p));
    return a;
}
__device__ __forceinline__ void cp_async16(uint32_t dst, const void* src) {
    asm volatile("cp.async.cg.shared.global [%0], [%1], 16;"
                 :: "r"(dst), "l"(src) : "memory");
}
__device__ __forceinline__ void cp_commit() {
    asm volatile("cp.async.commit_group;" ::: "memory");
}
template <int N>
__device__ __forceinline__ void cp_wait() {
    asm volatile("cp.async.wait_group %0;" :: "n"(N) : "memory");
}
__device__ __forceinline__ void ldsm_x4(uint32_t* r, uint32_t addr) {
    asm volatile("ldmatrix.sync.aligned.m8n8.x4.shared.b16 {%0,%1,%2,%3}, [%4];"
                 : "=r"(r[0]), "=r"(r[1]), "=r"(r[2]), "=r"(r[3]) : "r"(addr));
}
__device__ __forceinline__ void ldsm_x2(uint32_t* r, uint32_t addr) {
    asm volatile("ldmatrix.sync.aligned.m8n8.x2.shared.b16 {%0,%1}, [%2];"
                 : "=r"(r[0]), "=r"(r[1]) : "r"(addr));
}
__device__ __forceinline__ void mma16816(float* d, const uint32_t* a, const uint32_t* b) {
    asm volatile(
        "mma.sync.aligned.m16n8k16.row.col.f32.bf16.bf16.f32 "
        "{%0,%1,%2,%3}, {%4,%5,%6,%7}, {%8,%9}, {%0,%1,%2,%3};"
        : "+f"(d[0]), "+f"(d[1]), "+f"(d[2]), "+f"(d[3])
        : "r"(a[0]), "r"(a[1]), "r"(a[2]), "r"(a[3]), "r"(b[0]), "r"(b[1]));
}

// ---------------------------------------------------------------------------
// Kernel 0: fp32 -> bf16 conversion of A and bank
// ---------------------------------------------------------------------------
#define A_F4   (N_ROWS * DIM / 4)          // 524288
#define LUT_F4 (NUM_PIDS * DIM / 4)        // 354048
#define CQ_F4  (NUM_CQ * DIM / 4)          // 320000
#define TOT_F4 (A_F4 + LUT_F4 + CQ_F4)

__global__ void cvt_kernel(const float* __restrict__ A,
                           const float* __restrict__ lut,
                           const float* __restrict__ cq) {
    int i = blockIdx.x * blockDim.x + threadIdx.x;
    if (i >= TOT_F4) return;
    const float4* src;
    __nv_bfloat16* dst;
    if (i < A_F4) {
        src = (const float4*)A + i;
        dst = g_Abf + (size_t)i * 4;
    } else if (i < A_F4 + LUT_F4) {
        int j = i - A_F4;
        src = (const float4*)lut + j;
        dst = g_Bbf + (size_t)j * 4;
    } else {
        int j = i - A_F4 - LUT_F4;
        src = (const float4*)cq + j;
        dst = g_Bbf + (size_t)(LUT_F4 + j) * 4;
    }
    float4 v = *src;
    ushort4 o;
    o.x = __bfloat16_as_ushort(__float2bfloat16_rn(v.x));
    o.y = __bfloat16_as_ushort(__float2bfloat16_rn(v.y));
    o.z = __bfloat16_as_ushort(__float2bfloat16_rn(v.z));
    o.w = __bfloat16_as_ushort(__float2bfloat16_rn(v.w));
    *reinterpret_cast<ushort4*>(dst) = o;
}

// ---------------------------------------------------------------------------
// Kernel 1: mma.sync bf16 GEMM (128x128 tile, K=256) + fused exp-rowsum
// ---------------------------------------------------------------------------
__global__ __launch_bounds__(256)
void oim_mma_kernel(const float* __restrict__ rel, const int* __restrict__ label)
{
    __shared__ __align__(16) __nv_bfloat16 smA[2][BM * ASTRIDE];  // 2 x 10240 B
    __shared__ __align__(16) __nv_bfloat16 smB[2][BN * ASTRIDE];  // 2 x 10240 B
    __shared__ float relS[BN];
    __shared__ int   lblS[BM];
    __shared__ float red[BM * 4];

    const int tid = threadIdx.x;
    const int wid = tid >> 5;
    const int lane = tid & 31;
    const int warp_row = wid >> 2;        // 0..1  -> 64 rows each
    const int warp_col = wid & 3;         // 0..3  -> 32 cols each
    const int g = lane >> 2;              // 0..7
    const int t = lane & 3;               // 0..3

    const int bn = blockIdx.x;            // 0..82
    const int bm = blockIdx.y;            // 0..63
    const int row0 = bm * BM;
    const int col0 = bn * BN;

    // rel / label staging
    if (tid < BN) {
        int c = col0 + tid;
        relS[tid] = (c < L_TOT) ? rel[c] * OIM_SCALAR : 0.0f;
    }
    if (tid < BM) lblS[tid] = label[row0 + tid];

    const uint32_t smA_u = smem_u32(&smA[0][0]);
    const uint32_t smB_u = smem_u32(&smB[0][0]);
    const uint32_t STAGE = BM * ASTRIDE * 2;   // 10240 bytes

    // global->shared load descriptors (2 x 16B chunks per thread per tile)
    // chunk c: row m = c>>2, k-offset (c&3)*8 bf16
    const int c0i = tid, c1i = tid + 256;
    const int m0 = c0i >> 2, ko0 = (c0i & 3) * 8;
    const int m1 = c1i >> 2, ko1 = (c1i & 3) * 8;
    const uint32_t dstA0 = smA_u + (uint32_t)(m0 * ASTRIDE + ko0) * 2;
    const uint32_t dstA1 = smA_u + (uint32_t)(m1 * ASTRIDE + ko1) * 2;
    const uint32_t dstB0 = smB_u + (uint32_t)(m0 * ASTRIDE + ko0) * 2;
    const uint32_t dstB1 = smB_u + (uint32_t)(m1 * ASTRIDE + ko1) * 2;
    const __nv_bfloat16* srcA0 = g_Abf + (size_t)(row0 + m0) * DIM + ko0;
    const __nv_bfloat16* srcA1 = g_Abf + (size_t)(row0 + m1) * DIM + ko1;
    const __nv_bfloat16* srcB0 = g_Bbf + (size_t)(col0 + m0) * DIM + ko0;
    const __nv_bfloat16* srcB1 = g_Bbf + (size_t)(col0 + m1) * DIM + ko1;

    // ldmatrix per-lane address offsets
    const uint32_t aOff = smA_u +
        (uint32_t)(((warp_row * 64 + (lane & 15)) * ASTRIDE) + ((lane >> 4) << 3)) * 2;
    const uint32_t bOff = smB_u +
        (uint32_t)(((warp_col * 32 + (lane & 7)) * ASTRIDE) + (((lane >> 3) & 1) << 3)) * 2;

    float acc[4][4][4];
#pragma unroll
    for (int mi = 0; mi < 4; mi++)
#pragma unroll
        for (int ni = 0; ni < 4; ni++)
#pragma unroll
            for (int h = 0; h < 4; h++)
                acc[mi][ni][h] = 0.0f;

    // prefetch stage 0 (kc = 0)
    cp_async16(dstA0, srcA0);
    cp_async16(dstA1, srcA1);
    cp_async16(dstB0, srcB0);
    cp_async16(dstB1, srcB1);
    cp_commit();

#pragma unroll
    for (int kc = 0; kc < 8; kc++) {
        const int cur = kc & 1;
        if (kc < 7) {
            const int nxt = (kc + 1) & 1;
            const uint32_t so = nxt * STAGE;
            const int gko = (kc + 1) * BK;
            cp_async16(dstA0 + so, srcA0 + gko);
            cp_async16(dstA1 + so, srcA1 + gko);
            cp_async16(dstB0 + so, srcB0 + gko);
            cp_async16(dstB1 + so, srcB1 + gko);
            cp_commit();
            cp_wait<1>();
        } else {
            cp_wait<0>();
        }
        __syncthreads();

        const uint32_t aBase = aOff + cur * STAGE;
        const uint32_t bBase = bOff + cur * STAGE;
#pragma unroll
        for (int ks = 0; ks < 2; ks++) {      // two k16 steps per 32-chunk
            uint32_t a[4][4], b[4][2];
#pragma unroll
            for (int mi = 0; mi < 4; mi++)
                ldsm_x4(a[mi], aBase + (uint32_t)(mi * 16 * ASTRIDE + ks * 16) * 2);
#pragma unroll
            for (int ni = 0; ni < 4; ni++)
                ldsm_x2(b[ni], bBase + (uint32_t)(ni * 8 * ASTRIDE + ks * 16) * 2);
#pragma unroll
            for (int mi = 0; mi < 4; mi++)
#pragma unroll
                for (int ni = 0; ni < 4; ni++)
                    mma16816(acc[mi][ni], a[mi], b[ni]);
        }
        __syncthreads();
    }

    // ---- fused epilogue: logits -> exp row-sums + label logit capture ----
#pragma unroll
    for (int mi = 0; mi < 4; mi++) {
        const int rl0 = warp_row * 64 + mi * 16 + g;
        const int rl1 = rl0 + 8;
        const int lbl0 = lblS[rl0];
        const int lbl1 = lblS[rl1];
        float s0 = 0.0f, s1 = 0.0f;
#pragma unroll
        for (int ni = 0; ni < 4; ni++) {
#pragma unroll
            for (int h = 0; h < 2; h++) {
                const int lc = warp_col * 32 + ni * 8 + t * 2 + h;
                const int c = col0 + lc;
                const float rs = relS[lc];
                const float l0 = acc[mi][ni][h] * rs;
                const float l1 = acc[mi][ni][2 + h] * rs;
                if (c < L_TOT) {
                    s0 += __expf(l0);
                    s1 += __expf(l1);
                }
                if (c == lbl0) g_labellogit[row0 + rl0] = l0;   // unique writer
                if (c == lbl1) g_labellogit[row0 + rl1] = l1;
            }
        }
        s0 += __shfl_xor_sync(0xFFFFFFFFu, s0, 1);
        s0 += __shfl_xor_sync(0xFFFFFFFFu, s0, 2);
        s1 += __shfl_xor_sync(0xFFFFFFFFu, s1, 1);
        s1 += __shfl_xor_sync(0xFFFFFFFFu, s1, 2);
        if (t == 0) {
            red[rl0 * 4 + warp_col] = s0;
            red[rl1 * 4 + warp_col] = s1;
        }
    }
    __syncthreads();
    if (tid < BM) {
        float s = red[tid * 4 + 0] + red[tid * 4 + 1]
                + red[tid * 4 + 2] + red[tid * 4 + 3];
        g_partial[bn][row0 + tid] = s;
    }
}

// ---------------------------------------------------------------------------
// Kernel 2: per-row loss (deterministic fixed-order sum over column blocks)
// ---------------------------------------------------------------------------
__global__ void oim_rowloss_kernel(const int* __restrict__ label) {
    int i = blockIdx.x * blockDim.x + threadIdx.x;
    if (i >= N_ROWS) return;
    float s = 0.0f;
#pragma unroll 4
    for (int b = 0; b < NCB; b++)
        s += g_partial[b][i];
    int lbl = label[i];
    bool valid = (lbl != IGNORE_IDX);
    g_rowloss[i]  = valid ? (logf(s) - g_labellogit[i]) : 0.0f;
    g_rowvalid[i] = valid ? 1.0f : 0.0f;
}

// ---------------------------------------------------------------------------
// Kernel 3: final deterministic reduction
// ---------------------------------------------------------------------------
__global__ void oim_final_kernel(float* __restrict__ out) {
    __shared__ float ssum[1024];
    __shared__ float scnt[1024];
    int t = threadIdx.x;
    float s = 0.0f, c = 0.0f;
    for (int i = t; i < N_ROWS; i += 1024) {
        s += g_rowloss[i];
        c += g_rowvalid[i];
    }
    ssum[t] = s;
    scnt[t] = c;
    __syncthreads();
    for (int off = 512; off > 0; off >>= 1) {
        if (t < off) {
            ssum[t] += ssum[t + off];
            scnt[t] += scnt[t + off];
        }
        __syncthreads();
    }
    if (t == 0)
        out[0] = ssum[0] / fmaxf(scnt[0], 1.0f);
}

// ---------------------------------------------------------------------------
extern "C" void kernel_launch(void* const* d_in, const int* in_sizes, int n_in,
                              void* d_out, int out_size) {
    const float* inputs = (const float*)d_in[0];   // [8192, 256]
    const int*   label  = (const int*)  d_in[1];   // [8192]
    const float* lut    = (const float*)d_in[3];   // [5532, 256]
    const float* cq     = (const float*)d_in[4];   // [5000, 256]
    const float* rel    = (const float*)d_in[5];   // [10532]
    float* out = (float*)d_out;

    cvt_kernel<<<(TOT_F4 + 255) / 256, 256>>>(inputs, lut, cq);

    dim3 grid(NCB, N_ROWS / BM);   // 83 x 64
    oim_mma_kernel<<<grid, 256>>>(rel, label);

    oim_rowloss_kernel<<<(N_ROWS + 255) / 256, 256>>>(label);

    oim_final_kernel<<<1, 1024>>>(out);
}

// round 4
// speedup vs baseline: 6.1569x; 1.0451x over previous
#include <cuda_runtime.h>
#include <cuda_bf16.h>
#include <math.h>
#include <stdint.h>

// ---------------- problem constants ----------------
#define N_ROWS     8192
#define DIM        256
#define NUM_PIDS   5532
#define NUM_CQ     5000
#define L_TOT      (NUM_PIDS + NUM_CQ)   // 10532
#define IGNORE_IDX 5554
#define OIM_SCALAR 30.0f

// ---------------- tiling ----------------
#define BM 128
#define BN 128
#define BK 32
#define NSTAGE 4
#define NCB ((L_TOT + BN - 1) / BN)      // 83 column blocks
#define B_PAD (NCB * BN)                 // 10624 padded bank rows
#define ASTRIDE 40                       // bf16 elems per smem row (32 + 8 pad)

// dynamic smem layout (bytes)
#define STAGE_BYTES (BM * ASTRIDE * 2)          // 10240
#define OFF_SMA  0
#define OFF_SMB  (NSTAGE * STAGE_BYTES)         // 40960
#define OFF_REL  (2 * NSTAGE * STAGE_BYTES)     // 81920
#define OFF_LBL  (OFF_REL + BN * 4)             // 82432
#define OFF_RED  (OFF_LBL + BM * 4)             // 82944
#define SMEM_TOTAL (OFF_RED + BM * 4 * 4)       // 84992

// ---------------- device scratch (zero-initialized globals) ----------------
__device__ __nv_bfloat16 g_Abf[N_ROWS * DIM];
__device__ __nv_bfloat16 g_Bbf[B_PAD * DIM];   // rows >= L_TOT stay 0 forever
__device__ float g_partial[NCB][N_ROWS];
__device__ float g_labellogit[N_ROWS];
__device__ float g_bsum[32];
__device__ float g_bcnt[32];

// ---------------- PTX helpers (sm_80+, valid under compute_100) ----------
__device__ __forceinline__ uint32_t smem_u32(const void* p) {
    uint32_t a;
    asm("{ .reg .u64 t; cvta.to.shared.u64 t, %1; cvt.u32.u64 %0, t; }"
        : "=r"(a) : "l"(p));
    return a;
}
__device__ __forceinline__ void cp_async16(uint32_t dst, const void* src) {
    asm volatile("cp.async.cg.shared.global [%0], [%1], 16;"
                 :: "r"(dst), "l"(src) : "memory");
}
__device__ __forceinline__ void cp_commit() {
    asm volatile("cp.async.commit_group;" ::: "memory");
}
template <int N>
__device__ __forceinline__ void cp_wait() {
    asm volatile("cp.async.wait_group %0;" :: "n"(N) : "memory");
}
__device__ __forceinline__ void ldsm_x4(uint32_t* r, uint32_t addr) {
    asm volatile("ldmatrix.sync.aligned.m8n8.x4.shared.b16 {%0,%1,%2,%3}, [%4];"
                 : "=r"(r[0]), "=r"(r[1]), "=r"(r[2]), "=r"(r[3]) : "r"(addr));
}
__device__ __forceinline__ void ldsm_x2(uint32_t* r, uint32_t addr) {
    asm volatile("ldmatrix.sync.aligned.m8n8.x2.shared.b16 {%0,%1}, [%2];"
                 : "=r"(r[0]), "=r"(r[1]) : "r"(addr));
}
__device__ __forceinline__ void mma16816(float* d, const uint32_t* a, const uint32_t* b) {
    asm volatile(
        "mma.sync.aligned.m16n8k16.row.col.f32.bf16.bf16.f32 "
        "{%0,%1,%2,%3}, {%4,%5,%6,%7}, {%8,%9}, {%0,%1,%2,%3};"
        : "+f"(d[0]), "+f"(d[1]), "+f"(d[2]), "+f"(d[3])
        : "r"(a[0]), "r"(a[1]), "r"(a[2]), "r"(a[3]), "r"(b[0]), "r"(b[1]));
}

// ---------------------------------------------------------------------------
// Kernel 0: fp32 -> bf16 conversion of A and bank
// ---------------------------------------------------------------------------
#define A_F4   (N_ROWS * DIM / 4)
#define LUT_F4 (NUM_PIDS * DIM / 4)
#define CQ_F4  (NUM_CQ * DIM / 4)
#define TOT_F4 (A_F4 + LUT_F4 + CQ_F4)

__global__ void cvt_kernel(const float* __restrict__ A,
                           const float* __restrict__ lut,
                           const float* __restrict__ cq) {
    int i = blockIdx.x * blockDim.x + threadIdx.x;
    if (i >= TOT_F4) return;
    const float4* src;
    __nv_bfloat16* dst;
    if (i < A_F4) {
        src = (const float4*)A + i;
        dst = g_Abf + (size_t)i * 4;
    } else if (i < A_F4 + LUT_F4) {
        int j = i - A_F4;
        src = (const float4*)lut + j;
        dst = g_Bbf + (size_t)j * 4;
    } else {
        int j = i - A_F4 - LUT_F4;
        src = (const float4*)cq + j;
        dst = g_Bbf + (size_t)(LUT_F4 + j) * 4;
    }
    float4 v = *src;
    ushort4 o;
    o.x = __bfloat16_as_ushort(__float2bfloat16_rn(v.x));
    o.y = __bfloat16_as_ushort(__float2bfloat16_rn(v.y));
    o.z = __bfloat16_as_ushort(__float2bfloat16_rn(v.z));
    o.w = __bfloat16_as_ushort(__float2bfloat16_rn(v.w));
    *reinterpret_cast<ushort4*>(dst) = o;
}

// ---------------------------------------------------------------------------
// Kernel 1: mma.sync bf16 GEMM, 4-stage cp.async pipeline, fused exp-rowsum
// ---------------------------------------------------------------------------
__global__ __launch_bounds__(256)
void oim_mma_kernel(const float* __restrict__ rel, const int* __restrict__ label)
{
    extern __shared__ __align__(16) char smem[];
    float* relS = (float*)(smem + OFF_REL);
    int*   lblS = (int*)(smem + OFF_LBL);
    float* red  = (float*)(smem + OFF_RED);

    const int tid = threadIdx.x;
    const int wid = tid >> 5;
    const int lane = tid & 31;
    const int warp_row = wid >> 2;        // 0..1
    const int warp_col = wid & 3;         // 0..3
    const int g = lane >> 2;
    const int t = lane & 3;

    const int bn = blockIdx.x;            // 0..82
    const int bm = blockIdx.y;            // 0..63
    const int row0 = bm * BM;
    const int col0 = bn * BN;

    if (tid < BN) {
        int c = col0 + tid;
        relS[tid] = (c < L_TOT) ? rel[c] * OIM_SCALAR : 0.0f;
    }
    if (tid < BM) lblS[tid] = label[row0 + tid];

    const uint32_t smA_u = smem_u32(smem + OFF_SMA);
    const uint32_t smB_u = smem_u32(smem + OFF_SMB);

    // global->shared descriptors: 2 x 16B chunks per thread per tile half
    const int c0i = tid, c1i = tid + 256;
    const int m0 = c0i >> 2, ko0 = (c0i & 3) * 8;
    const int m1 = c1i >> 2, ko1 = (c1i & 3) * 8;
    const uint32_t dstA0 = smA_u + (uint32_t)(m0 * ASTRIDE + ko0) * 2;
    const uint32_t dstA1 = smA_u + (uint32_t)(m1 * ASTRIDE + ko1) * 2;
    const uint32_t dstB0 = smB_u + (uint32_t)(m0 * ASTRIDE + ko0) * 2;
    const uint32_t dstB1 = smB_u + (uint32_t)(m1 * ASTRIDE + ko1) * 2;
    const __nv_bfloat16* srcA0 = g_Abf + (size_t)(row0 + m0) * DIM + ko0;
    const __nv_bfloat16* srcA1 = g_Abf + (size_t)(row0 + m1) * DIM + ko1;
    const __nv_bfloat16* srcB0 = g_Bbf + (size_t)(col0 + m0) * DIM + ko0;
    const __nv_bfloat16* srcB1 = g_Bbf + (size_t)(col0 + m1) * DIM + ko1;

    // ldmatrix per-lane base offsets
    const uint32_t aOff = smA_u +
        (uint32_t)(((warp_row * 64 + (lane & 15)) * ASTRIDE) + ((lane >> 4) << 3)) * 2;
    const uint32_t bOff = smB_u +
        (uint32_t)(((warp_col * 32 + (lane & 7)) * ASTRIDE) + (((lane >> 3) & 1) << 3)) * 2;

    float acc[4][4][4];
#pragma unroll
    for (int mi = 0; mi < 4; mi++)
#pragma unroll
        for (int ni = 0; ni < 4; ni++)
#pragma unroll
            for (int h = 0; h < 4; h++)
                acc[mi][ni][h] = 0.0f;

    // prologue: prefetch stages 0..2
#pragma unroll
    for (int s = 0; s < NSTAGE - 1; s++) {
        const uint32_t so = (uint32_t)s * STAGE_BYTES;
        const int gko = s * BK;
        cp_async16(dstA0 + so, srcA0 + gko);
        cp_async16(dstA1 + so, srcA1 + gko);
        cp_async16(dstB0 + so, srcB0 + gko);
        cp_async16(dstB1 + so, srcB1 + gko);
        cp_commit();
    }

#pragma unroll
    for (int kc = 0; kc < 8; kc++) {
        // wait until stage kc is resident (allow up to 2 younger groups in flight)
        if (kc <= 5)      cp_wait<2>();
        else if (kc == 6) cp_wait<1>();
        else              cp_wait<0>();
        __syncthreads();

        // issue prefetch for stage kc+3 (slot reused from iter kc-1, safe after barrier)
        if (kc < 5) {
            const uint32_t so = (uint32_t)((kc + 3) & (NSTAGE - 1)) * STAGE_BYTES;
            const int gko = (kc + 3) * BK;
            cp_async16(dstA0 + so, srcA0 + gko);
            cp_async16(dstA1 + so, srcA1 + gko);
            cp_async16(dstB0 + so, srcB0 + gko);
            cp_async16(dstB1 + so, srcB1 + gko);
            cp_commit();
        }

        const uint32_t so = (uint32_t)(kc & (NSTAGE - 1)) * STAGE_BYTES;
        const uint32_t aBase = aOff + so;
        const uint32_t bBase = bOff + so;
#pragma unroll
        for (int ks = 0; ks < 2; ks++) {
            uint32_t a[4][4], b[4][2];
#pragma unroll
            for (int mi = 0; mi < 4; mi++)
                ldsm_x4(a[mi], aBase + (uint32_t)(mi * 16 * ASTRIDE + ks * 16) * 2);
#pragma unroll
            for (int ni = 0; ni < 4; ni++)
                ldsm_x2(b[ni], bBase + (uint32_t)(ni * 8 * ASTRIDE + ks * 16) * 2);
#pragma unroll
            for (int mi = 0; mi < 4; mi++)
#pragma unroll
                for (int ni = 0; ni < 4; ni++)
                    mma16816(acc[mi][ni], a[mi], b[ni]);
        }
        // no trailing barrier: next iteration's barrier protects slot reuse
    }

    // ---- fused epilogue ----
#pragma unroll
    for (int mi = 0; mi < 4; mi++) {
        const int rl0 = warp_row * 64 + mi * 16 + g;
        const int rl1 = rl0 + 8;
        const int lbl0 = lblS[rl0];
        const int lbl1 = lblS[rl1];
        float s0 = 0.0f, s1 = 0.0f;
#pragma unroll
        for (int ni = 0; ni < 4; ni++) {
#pragma unroll
            for (int h = 0; h < 2; h++) {
                const int lc = warp_col * 32 + ni * 8 + t * 2 + h;
                const int c = col0 + lc;
                const float rs = relS[lc];
                const float l0 = acc[mi][ni][h] * rs;
                const float l1 = acc[mi][ni][2 + h] * rs;
                if (c < L_TOT) {
                    s0 += __expf(l0);
                    s1 += __expf(l1);
                }
                if (c == lbl0) g_labellogit[row0 + rl0] = l0;   // unique writer
                if (c == lbl1) g_labellogit[row0 + rl1] = l1;
            }
        }
        s0 += __shfl_xor_sync(0xFFFFFFFFu, s0, 1);
        s0 += __shfl_xor_sync(0xFFFFFFFFu, s0, 2);
        s1 += __shfl_xor_sync(0xFFFFFFFFu, s1, 1);
        s1 += __shfl_xor_sync(0xFFFFFFFFu, s1, 2);
        if (t == 0) {
            red[rl0 * 4 + warp_col] = s0;
            red[rl1 * 4 + warp_col] = s1;
        }
    }
    __syncthreads();
    if (tid < BM) {
        float s = red[tid * 4 + 0] + red[tid * 4 + 1]
                + red[tid * 4 + 2] + red[tid * 4 + 3];
        g_partial[bn][row0 + tid] = s;
    }
}

// ---------------------------------------------------------------------------
// Kernel 2: per-row loss + block reduction (32 blocks x 256)
// ---------------------------------------------------------------------------
__global__ __launch_bounds__(256)
void oim_rowloss_kernel(const int* __restrict__ label) {
    __shared__ float wsum[8], wcnt[8];
    const int i = blockIdx.x * 256 + threadIdx.x;    // row id, 32*256 = 8192
    float s = 0.0f;
#pragma unroll 4
    for (int b = 0; b < NCB; b++)
        s += g_partial[b][i];
    const int lbl = label[i];
    const bool valid = (lbl != IGNORE_IDX);
    float loss = valid ? (logf(s) - g_labellogit[i]) : 0.0f;
    float cnt  = valid ? 1.0f : 0.0f;
#pragma unroll
    for (int off = 16; off > 0; off >>= 1) {
        loss += __shfl_down_sync(0xFFFFFFFFu, loss, off);
        cnt  += __shfl_down_sync(0xFFFFFFFFu, cnt, off);
    }
    const int lane = threadIdx.x & 31;
    const int w = threadIdx.x >> 5;
    if (lane == 0) { wsum[w] = loss; wcnt[w] = cnt; }
    __syncthreads();
    if (threadIdx.x == 0) {
        float bs = 0.0f, bc = 0.0f;
#pragma unroll
        for (int k = 0; k < 8; k++) { bs += wsum[k]; bc += wcnt[k]; }
        g_bsum[blockIdx.x] = bs;
        g_bcnt[blockIdx.x] = bc;
    }
}

// ---------------------------------------------------------------------------
// Kernel 3: final reduction (1 warp)
// ---------------------------------------------------------------------------
__global__ void oim_final_kernel(float* __restrict__ out) {
    const int lane = threadIdx.x;
    float s = g_bsum[lane];
    float c = g_bcnt[lane];
#pragma unroll
    for (int off = 16; off > 0; off >>= 1) {
        s += __shfl_down_sync(0xFFFFFFFFu, s, off);
        c += __shfl_down_sync(0xFFFFFFFFu, c, off);
    }
    if (lane == 0)
        out[0] = s / fmaxf(c, 1.0f);
}

// ---------------------------------------------------------------------------
extern "C" void kernel_launch(void* const* d_in, const int* in_sizes, int n_in,
                              void* d_out, int out_size) {
    const float* inputs = (const float*)d_in[0];   // [8192, 256]
    const int*   label  = (const int*)  d_in[1];   // [8192]
    const float* lut    = (const float*)d_in[3];   // [5532, 256]
    const float* cq     = (const float*)d_in[4];   // [5000, 256]
    const float* rel    = (const float*)d_in[5];   // [10532]
    float* out = (float*)d_out;

    static bool attr_set = false;
    if (!attr_set) {
        cudaFuncSetAttribute(oim_mma_kernel,
                             cudaFuncAttributeMaxDynamicSharedMemorySize, SMEM_TOTAL);
        attr_set = true;
    }

    cvt_kernel<<<(TOT_F4 + 255) / 256, 256>>>(inputs, lut, cq);

    dim3 grid(NCB, N_ROWS / BM);   // 83 x 64
    oim_mma_kernel<<<grid, 256, SMEM_TOTAL>>>(rel, label);

    oim_rowloss_kernel<<<32, 256>>>(label);

    oim_final_kernel<<<1, 32>>>(out);
}